// round 16
// baseline (speedup 1.0000x reference)
#include <cuda_runtime.h>
#include <cuda_bf16.h>
#include <stdint.h>

#define NROW 4096
#define DIM  1024
#define NT   256
#define RS   40          // padded smem row stride (bf16 elems) for conflict-free ldmatrix
#define NGEMM 528        // lower-triangular 128x128 tiles

// Static device scratch (no runtime allocation allowed).
__device__ __nv_bfloat16 g_Xb[(size_t)NROW * DIM];     // 8 MB normalized embeddings
__device__ __nv_bfloat16 g_SIMh[(size_t)NROW * NROW];  // 32 MB similarity matrix (bf16)
__device__ unsigned char g_cls[NROW];
__device__ float g_rowloss[NROW];
__device__ unsigned int g_panel[32];                   // per-row-panel completion (32 each)
__device__ unsigned int g_done;                        // finished row blocks

// Monotone bf16-bits <-> 16-bit key (ascending order preserved)
__device__ __forceinline__ unsigned int h2k(unsigned int u) {
    return (u & 0x8000u) ? ((~u) & 0xFFFFu) : (u | 0x8000u);
}
__device__ __forceinline__ float k2f16(unsigned int k) {
    unsigned int u = (k & 0x8000u) ? (k & 0x7FFFu) : ((~k) & 0xFFFFu);
    return __uint_as_float(u << 16);
}
__device__ __forceinline__ float h2f(unsigned int u) {
    return __uint_as_float(u << 16);
}

// ---------------------------------------------------------------------------
// Classes + counter reset. Reference declares int64 targets, but JAX without
// x64 emits int32 -> sniff layout (all odd words zero => int64).
__global__ __launch_bounds__(1024) void cls_kernel(const int* __restrict__ tgt32) {
    __shared__ int s_any;
    const int t = threadIdx.x;
    if (t == 0) s_any = 0;
    if (t < 32) g_panel[t] = 0u;
    if (t == 32) g_done = 0u;
    __syncthreads();
    int any = 0;
    for (int j = t; j < NROW / 2; j += 1024)
        any |= (tgt32[2 * j + 1] != 0);
    if (any) atomicOr(&s_any, 1);
    __syncthreads();
    const bool is64 = (s_any == 0);
    for (int i = t; i < NROW; i += 1024)
        g_cls[i] = (unsigned char)(is64 ? tgt32[2 * i] : tgt32[i]);
}

// ---------------------------------------------------------------------------
// Single-pass normalize: each thread owns one float4 of the row.
__global__ __launch_bounds__(256) void normalize_kernel(const float* __restrict__ emb) {
    const int i = blockIdx.x;
    const int t = threadIdx.x;
    const int lane = t & 31;
    const int wid  = t >> 5;
    __shared__ float s[8];

    float4 v = *(const float4*)(emb + (size_t)i * DIM + t * 4);
    float ss = v.x * v.x + v.y * v.y + v.z * v.z + v.w * v.w;
#pragma unroll
    for (int o = 16; o > 0; o >>= 1) ss += __shfl_xor_sync(0xFFFFFFFFu, ss, o);
    if (lane == 0) s[wid] = ss;
    __syncthreads();
    float tot = 0.f;
#pragma unroll
    for (int w = 0; w < 8; w++) tot += s[w];
    const float norm = fmaxf(sqrtf(tot), 1e-12f);

    unsigned int u0 = (unsigned int)__bfloat16_as_ushort(__float2bfloat16(v.x / norm));
    unsigned int u1 = (unsigned int)__bfloat16_as_ushort(__float2bfloat16(v.y / norm));
    unsigned int u2 = (unsigned int)__bfloat16_as_ushort(__float2bfloat16(v.z / norm));
    unsigned int u3 = (unsigned int)__bfloat16_as_ushort(__float2bfloat16(v.w / norm));
    uint2 pk;
    pk.x = u0 | (u1 << 16);
    pk.y = u2 | (u3 << 16);
    *(uint2*)(g_Xb + (size_t)i * DIM + t * 4) = pk;
}

// ---------------------------------------------------------------------------
__device__ __forceinline__ void cp16(unsigned int smem_dst, const void* gsrc) {
    asm volatile("cp.async.cg.shared.global [%0], [%1], 16;\n" :: "r"(smem_dst), "l"(gsrc));
}
__device__ __forceinline__ void cp_commit() { asm volatile("cp.async.commit_group;\n"); }
__device__ __forceinline__ void cp_wait0() { asm volatile("cp.async.wait_group 0;\n"); }

// ---------------------------------------------------------------------------
// FUSED kernel: blocks 0..527 = symmetric bf16 GEMM tiles (R8/R14-proven);
// blocks 528.. = per-row loss (R15-proven), spin-waiting on panel counters.
// Row-panel P is complete after exactly 32 tile-writers signal it.
__global__ __launch_bounds__(NT) void fused_kernel(float* __restrict__ out) {
    __shared__ __align__(16) char smbuf[40960];
    __shared__ unsigned int s_hist[256];
    __shared__ unsigned int s_wtot[8];
    __shared__ float        s_red[8];
    __shared__ unsigned int sh_sel, sh_r, sh_h, sh_pcnt, sh_last;

    const int t    = threadIdx.x;
    const int lane = t & 31;
    const int wid  = t >> 5;

    if (blockIdx.x < NGEMM) {
        // ===================== GEMM tile =====================
        typedef __nv_bfloat16 Tile[128][RS];
        Tile* sA = reinterpret_cast<Tile*>(smbuf);
        Tile* sB = reinterpret_cast<Tile*>(smbuf + 2 * 128 * RS * 2);
        float (*tr)[132] = reinterpret_cast<float (*)[132]>(smbuf);

        const int wm = (wid >> 2) * 64;
        const int wn = (wid & 3) * 32;

        const int b = blockIdx.x;
        int p = (int)((sqrtf(8.f * (float)b + 1.f) - 1.f) * 0.5f);
        while ((p + 1) * (p + 2) / 2 <= b) p++;
        while (p * (p + 1) / 2 > b) p--;
        const int q  = b - p * (p + 1) / 2;
        const int bi = p * 128;
        const int bj = q * 128;

        float acc[4][4][4];
#pragma unroll
        for (int mt = 0; mt < 4; mt++)
#pragma unroll
            for (int nt = 0; nt < 4; nt++)
#pragma unroll
                for (int r = 0; r < 4; r++) acc[mt][nt][r] = 0.f;

        auto load_stage = [&](int buf, int k0) {
#pragma unroll
            for (int c = t; c < 512; c += 256) {
                int row = c >> 2, off = (c & 3) * 8;
                cp16((unsigned int)__cvta_generic_to_shared(&sA[buf][row][off]),
                     g_Xb + (size_t)(bi + row) * DIM + k0 + off);
                cp16((unsigned int)__cvta_generic_to_shared(&sB[buf][row][off]),
                     g_Xb + (size_t)(bj + row) * DIM + k0 + off);
            }
        };

        load_stage(0, 0);
        cp_commit();
        cp_wait0();
        __syncthreads();

        for (int s = 0; s < DIM / 32; s++) {
            const int cbuf = s & 1;
            if (s + 1 < DIM / 32) {
                load_stage((s + 1) & 1, (s + 1) * 32);
                cp_commit();
            }
#pragma unroll
            for (int ks = 0; ks < 2; ks++) {
                unsigned int a[4][4], bb[4][2];
#pragma unroll
                for (int mt = 0; mt < 4; mt++) {
                    unsigned int addr = (unsigned int)__cvta_generic_to_shared(
                        &sA[cbuf][wm + mt * 16 + (lane & 15)][ks * 16 + (lane >> 4) * 8]);
                    asm volatile("ldmatrix.sync.aligned.m8n8.x4.shared.b16 {%0,%1,%2,%3}, [%4];"
                                 : "=r"(a[mt][0]), "=r"(a[mt][1]), "=r"(a[mt][2]), "=r"(a[mt][3])
                                 : "r"(addr));
                }
#pragma unroll
                for (int nt = 0; nt < 4; nt++) {
                    unsigned int addr = (unsigned int)__cvta_generic_to_shared(
                        &sB[cbuf][wn + nt * 8 + (lane & 7)][ks * 16 + ((lane >> 3) & 1) * 8]);
                    asm volatile("ldmatrix.sync.aligned.m8n8.x2.shared.b16 {%0,%1}, [%2];"
                                 : "=r"(bb[nt][0]), "=r"(bb[nt][1]) : "r"(addr));
                }
#pragma unroll
                for (int mt = 0; mt < 4; mt++)
#pragma unroll
                    for (int nt = 0; nt < 4; nt++) {
                        asm volatile(
                            "mma.sync.aligned.m16n8k16.row.col.f32.bf16.bf16.f32 "
                            "{%0,%1,%2,%3},{%4,%5,%6,%7},{%8,%9},{%0,%1,%2,%3};"
                            : "+f"(acc[mt][nt][0]), "+f"(acc[mt][nt][1]),
                              "+f"(acc[mt][nt][2]), "+f"(acc[mt][nt][3])
                            : "r"(a[mt][0]), "r"(a[mt][1]), "r"(a[mt][2]), "r"(a[mt][3]),
                              "r"(bb[nt][0]), "r"(bb[nt][1]));
                    }
            }
            if (s + 1 < DIM / 32) cp_wait0();
            __syncthreads();
        }

        // direct store of (bi, bj) tile
#pragma unroll
        for (int mt = 0; mt < 4; mt++) {
#pragma unroll
            for (int nt = 0; nt < 4; nt++) {
                int r0 = bi + wm + mt * 16 + (lane >> 2);
                int c0 = bj + wn + nt * 8 + (lane & 3) * 2;
                __nv_bfloat162 p01 = __floats2bfloat162_rn(acc[mt][nt][0], acc[mt][nt][1]);
                __nv_bfloat162 p23 = __floats2bfloat162_rn(acc[mt][nt][2], acc[mt][nt][3]);
                *(__nv_bfloat162*)(g_SIMh + (size_t)r0 * NROW + c0) = p01;
                *(__nv_bfloat162*)(g_SIMh + (size_t)(r0 + 8) * NROW + c0) = p23;
            }
        }

        // transposed store of (bj, bi) tile, staged via smem
        if (p != q) {
            for (int cc = 0; cc < 4; cc++) {
                __syncthreads();
                if ((wid & 3) == cc) {
#pragma unroll
                    for (int mt = 0; mt < 4; mt++)
#pragma unroll
                        for (int nt = 0; nt < 4; nt++) {
                            int r0 = wm + mt * 16 + (lane >> 2);
                            int c0 = nt * 8 + (lane & 3) * 2;
                            tr[c0    ][r0    ] = acc[mt][nt][0];
                            tr[c0 + 1][r0    ] = acc[mt][nt][1];
                            tr[c0    ][r0 + 8] = acc[mt][nt][2];
                            tr[c0 + 1][r0 + 8] = acc[mt][nt][3];
                        }
                }
                __syncthreads();
                const int c = t >> 3;
                const int r = (t & 7) * 16;
                __nv_bfloat16* dst = g_SIMh + (size_t)(bj + cc * 32 + c) * NROW + bi + r;
#pragma unroll
                for (int k = 0; k < 4; k++) {
                    float4 f = *(float4*)(&tr[c][r + k * 4]);
                    __nv_bfloat162 lo = __floats2bfloat162_rn(f.x, f.y);
                    __nv_bfloat162 hi = __floats2bfloat162_rn(f.z, f.w);
                    uint2 w;
                    w.x = *(unsigned int*)&lo;
                    w.y = *(unsigned int*)&hi;
                    *(uint2*)(dst + k * 4) = w;
                }
            }
        }

        // completion signal: panel p (direct rows) and panel q (transposed rows)
        __threadfence();
        __syncthreads();
        if (t == 0) {
            atomicAdd(&g_panel[p], 1u);
            if (p != q) atomicAdd(&g_panel[q], 1u);
        }
        return;
    }

    // ===================== row-loss block =====================
    const int i = blockIdx.x - NGEMM;
    unsigned short* s_k   = reinterpret_cast<unsigned short*>(smbuf);          // 8 KB
    unsigned short* s_pos = reinterpret_cast<unsigned short*>(smbuf + 8192);   // 8 KB

    // wait for this row's panel (32 tile-writers)
    if (t == 0) {
        const int panel = i >> 7;
        while (atomicAdd(&g_panel[panel], 0u) < 32u) __nanosleep(128);
    }
    __syncthreads();

    const unsigned char myc = g_cls[i];
    const __nv_bfloat16* row = g_SIMh + (size_t)i * NROW;

    s_hist[t] = 0;
    if (t == 0) sh_pcnt = 0;
    __syncthreads();

    // ---- load pass: neg keys + pos compaction + round-0 hist + K + pos_max ----
    float pmax = -1e30f;
    int   kneg = 0;
#pragma unroll
    for (int c = 0; c < 2; c++) {
        const int j0 = (c * NT + t) * 8;
        uint4 kv = *(const uint4*)(row + j0);
        uint2 cw = *(const uint2*)(g_cls + j0);
        unsigned int hw[4] = {kv.x, kv.y, kv.z, kv.w};
        unsigned short kk[8];
#pragma unroll
        for (int e = 0; e < 8; e++) {
            const unsigned int u  = (hw[e >> 1] >> ((e & 1) * 16)) & 0xFFFFu;
            const unsigned int cl = ((e < 4 ? cw.x : cw.y) >> ((e & 3) * 8)) & 0xFFu;
            if (cl != (unsigned int)myc) {
                const unsigned int key = h2k(u);
                kk[e] = (unsigned short)key;
                kneg++;
                atomicAdd(&s_hist[key >> 8], 1u);
            } else {
                kk[e] = 0u;
                if (j0 + e != i) {
                    const unsigned int slot = atomicAdd(&sh_pcnt, 1u);
                    s_pos[slot] = (unsigned short)u;
                    pmax = fmaxf(pmax, h2f(u));
                }
            }
        }
        *(uint4*)(s_k + j0) = *(uint4*)kk;
    }
#pragma unroll
    for (int o = 16; o > 0; o >>= 1) {
        kneg += __shfl_xor_sync(0xFFFFFFFFu, kneg, o);
        pmax  = fmaxf(pmax, __shfl_xor_sync(0xFFFFFFFFu, pmax, o));
    }
    if (lane == 0) { s_wtot[wid] = (unsigned int)kneg; s_red[wid] = pmax; }
    __syncthreads();
    unsigned int K = 0; float pm = -1e30f;
#pragma unroll
    for (int w = 0; w < 8; w++) { K += s_wtot[w]; pm = fmaxf(pm, s_red[w]); }
    const int drop = max((int)floorf((float)K * 0.05f), 1);
    unsigned int r = (unsigned int)(drop + 1);
    const unsigned int pcnt = sh_pcnt;

    auto select_bucket = [&](unsigned int rr) {
        const unsigned int h = s_hist[t];
        unsigned int suf = h;
#pragma unroll
        for (int o = 1; o < 32; o <<= 1) {
            const unsigned int w = __shfl_down_sync(0xFFFFFFFFu, suf, o);
            if (lane + o < 32) suf += w;
        }
        if (lane == 0) s_wtot[wid] = suf;
        __syncthreads();
#pragma unroll
        for (int w = 0; w < 8; w++) if (w > wid) suf += s_wtot[w];
        if (suf >= rr && (suf - h) < rr) {
            sh_sel = (unsigned int)t;
            sh_r   = rr - (suf - h);
            sh_h   = h;
        }
        __syncthreads();
    };

    // round 0: top byte
    select_bucket(r);
    unsigned int prefix = sh_sel;
    r = sh_r;
    __syncthreads();

    // round 1: low byte -> full 16-bit key
    s_hist[t] = 0;
    __syncthreads();
#pragma unroll
    for (int c = 0; c < 2; c++) {
        const int j0 = (c * NT + t) * 8;
        uint4 kw = *(const uint4*)(s_k + j0);
        unsigned int hw[4] = {kw.x, kw.y, kw.z, kw.w};
#pragma unroll
        for (int e = 0; e < 8; e++) {
            const unsigned int k = (hw[e >> 1] >> ((e & 1) * 16)) & 0xFFFFu;
            if ((k >> 8) == prefix)
                atomicAdd(&s_hist[k & 255u], 1u);
        }
    }
    __syncthreads();
    select_bucket(r);
    const unsigned int keyT = (prefix << 8) | sh_sel;
    const float T = k2f16(keyT);                        // == neg_thresh (bf16-exact)
    const int   m = (int)sh_h + 1 - (int)sh_r;
    __syncthreads();

    // final: pos_loss over compact list; neg scan only if satisfiable
    const float thr   = T + 0.1f;
    const float lower = fmaxf(0.6f, pm) - 0.1f;
    float ploss = 0.f, ns = 0.f;

    for (unsigned int j = t; j < pcnt; j += NT) {
        const float v = h2f((unsigned int)s_pos[j]);
        if (v < thr) ploss += 1.0f - v;
    }
    if (T > lower) {
#pragma unroll
        for (int c = 0; c < 2; c++) {
            const int j0 = (c * NT + t) * 8;
            uint4 kw = *(const uint4*)(s_k + j0);
            unsigned int hw[4] = {kw.x, kw.y, kw.z, kw.w};
#pragma unroll
            for (int e = 0; e < 8; e++) {
                const unsigned int k = (hw[e >> 1] >> ((e & 1) * 16)) & 0xFFFFu;
                if (k) {
                    const float v = k2f16(k);
                    if (v < T && v > lower) ns += v;
                }
            }
        }
    }
#pragma unroll
    for (int o = 16; o > 0; o >>= 1) {
        ploss += __shfl_xor_sync(0xFFFFFFFFu, ploss, o);
        ns    += __shfl_xor_sync(0xFFFFFFFFu, ns, o);
    }
    if (lane == 0) { s_red[wid] = ploss; s_wtot[wid] = __float_as_uint(ns); }
    __syncthreads();

    if (t == 0) {
        float pl = 0.f, nss = 0.f;
#pragma unroll
        for (int w = 0; w < 8; w++) { pl += s_red[w]; nss += __uint_as_float(s_wtot[w]); }
        float loss = 0.f;
        if (pm > -1e29f) {
            loss = pl + nss;
            if (T > lower) loss += (float)m * T;
        }
        g_rowloss[i] = loss;
        __threadfence();
        sh_last = (atomicAdd(&g_done, 1u) == (unsigned int)(NROW - 1)) ? 1u : 0u;
    }
    __syncthreads();

    // last row block: deterministic fixed-order final reduction
    if (sh_last) {
        float* scratch = reinterpret_cast<float*>(smbuf);
        float a = 0.f;
        for (int j = t; j < NROW; j += NT) a += g_rowloss[j];
        scratch[t] = a;
        __syncthreads();
        for (int o = NT / 2; o > 0; o >>= 1) {
            if (t < o) scratch[t] += scratch[t + o];
            __syncthreads();
        }
        if (t == 0) out[0] = scratch[0] / (float)NROW;
    }
}

// ---------------------------------------------------------------------------
extern "C" void kernel_launch(void* const* d_in, const int* in_sizes, int n_in,
                              void* d_out, int out_size) {
    const float* emb   = (const float*)d_in[0];
    const int*   tgt32 = (const int*)d_in[1];
    float* out = (float*)d_out;

    cls_kernel<<<1, 1024>>>(tgt32);
    normalize_kernel<<<NROW, 256>>>(emb);
    fused_kernel<<<NGEMM + NROW, NT>>>(out);
}

// round 17
// speedup vs baseline: 1.3210x; 1.3210x over previous
#include <cuda_runtime.h>
#include <cuda_bf16.h>
#include <stdint.h>

#define NROW 4096
#define DIM  1024
#define NT   256
#define RS   40          // padded smem row stride (bf16 elems) for conflict-free ldmatrix
#define NGEMM 528        // lower-triangular 128x128 tiles

// Static device scratch (no runtime allocation allowed).
__device__ __nv_bfloat16 g_Xb[(size_t)NROW * DIM];     // 8 MB normalized embeddings
__device__ __nv_bfloat16 g_SIMh[(size_t)NROW * NROW];  // 32 MB similarity matrix (bf16)
__device__ unsigned char g_cls[NROW];
__device__ float g_rowloss[NROW];

// Monotone bf16-bits <-> 16-bit key (ascending order preserved)
__device__ __forceinline__ unsigned int h2k(unsigned int u) {   // u = bf16 bits (16)
    return (u & 0x8000u) ? ((~u) & 0xFFFFu) : (u | 0x8000u);
}
__device__ __forceinline__ float k2f16(unsigned int k) {
    unsigned int u = (k & 0x8000u) ? (k & 0x7FFFu) : ((~k) & 0xFFFFu);
    return __uint_as_float(u << 16);
}
__device__ __forceinline__ float h2f(unsigned int u) {          // bf16 bits -> float
    return __uint_as_float(u << 16);
}

// ---------------------------------------------------------------------------
// Single-pass normalize: each thread owns one float4 of the row.
__global__ __launch_bounds__(256) void normalize_kernel(const float* __restrict__ emb) {
    const int i = blockIdx.x;
    const int t = threadIdx.x;
    const int lane = t & 31;
    const int wid  = t >> 5;
    __shared__ float s[8];

    float4 v = *(const float4*)(emb + (size_t)i * DIM + t * 4);
    float ss = v.x * v.x + v.y * v.y + v.z * v.z + v.w * v.w;
#pragma unroll
    for (int o = 16; o > 0; o >>= 1) ss += __shfl_xor_sync(0xFFFFFFFFu, ss, o);
    if (lane == 0) s[wid] = ss;
    __syncthreads();
    float tot = 0.f;
#pragma unroll
    for (int w = 0; w < 8; w++) tot += s[w];
    const float norm = fmaxf(sqrtf(tot), 1e-12f);

    unsigned int u0 = (unsigned int)__bfloat16_as_ushort(__float2bfloat16(v.x / norm));
    unsigned int u1 = (unsigned int)__bfloat16_as_ushort(__float2bfloat16(v.y / norm));
    unsigned int u2 = (unsigned int)__bfloat16_as_ushort(__float2bfloat16(v.z / norm));
    unsigned int u3 = (unsigned int)__bfloat16_as_ushort(__float2bfloat16(v.w / norm));
    uint2 pk;
    pk.x = u0 | (u1 << 16);
    pk.y = u2 | (u3 << 16);
    *(uint2*)(g_Xb + (size_t)i * DIM + t * 4) = pk;
}

// ---------------------------------------------------------------------------
// SIM = X * X^T in bf16 tensor cores (R8/R14-proven). SYMMETRIC: 528 lower-
// triangular 128x128 tiles + ONE extra block (bid 528) that extracts classes
// (hidden under the GEMM; row_loss consumes g_cls only after this kernel).
__device__ __forceinline__ void cp16(unsigned int smem_dst, const void* gsrc) {
    asm volatile("cp.async.cg.shared.global [%0], [%1], 16;\n" :: "r"(smem_dst), "l"(gsrc));
}
__device__ __forceinline__ void cp_commit() { asm volatile("cp.async.commit_group;\n"); }
__device__ __forceinline__ void cp_wait0() { asm volatile("cp.async.wait_group 0;\n"); }

__global__ __launch_bounds__(256) void gemm_kernel(const int* __restrict__ tgt32) {
    __shared__ __align__(16) char smbuf[2 * 128 * RS * 2 * 2];

    const int t    = threadIdx.x;
    const int lane = t & 31;
    const int wid  = t >> 5;

    if (blockIdx.x == NGEMM) {
        // ---- class block: int64-vs-int32 sniff + extraction ----
        __shared__ int s_any;
        if (t == 0) s_any = 0;
        __syncthreads();
        int any = 0;
        for (int j = t; j < NROW / 2; j += 256)
            any |= (tgt32[2 * j + 1] != 0);
        if (any) atomicOr(&s_any, 1);
        __syncthreads();
        const bool is64 = (s_any == 0);
        for (int j = t; j < NROW; j += 256)
            g_cls[j] = (unsigned char)(is64 ? tgt32[2 * j] : tgt32[j]);
        return;
    }

    typedef __nv_bfloat16 Tile[128][RS];
    Tile* sA = reinterpret_cast<Tile*>(smbuf);
    Tile* sB = reinterpret_cast<Tile*>(smbuf + 2 * 128 * RS * 2);
    float (*tr)[132] = reinterpret_cast<float (*)[132]>(smbuf);

    const int wm = (wid >> 2) * 64;
    const int wn = (wid & 3) * 32;

    const int b = blockIdx.x;
    int p = (int)((sqrtf(8.f * (float)b + 1.f) - 1.f) * 0.5f);
    while ((p + 1) * (p + 2) / 2 <= b) p++;
    while (p * (p + 1) / 2 > b) p--;
    const int q  = b - p * (p + 1) / 2;
    const int bi = p * 128;
    const int bj = q * 128;

    float acc[4][4][4];
#pragma unroll
    for (int mt = 0; mt < 4; mt++)
#pragma unroll
        for (int nt = 0; nt < 4; nt++)
#pragma unroll
            for (int r = 0; r < 4; r++) acc[mt][nt][r] = 0.f;

    auto load_stage = [&](int buf, int k0) {
#pragma unroll
        for (int c = t; c < 512; c += 256) {
            int row = c >> 2, off = (c & 3) * 8;
            cp16((unsigned int)__cvta_generic_to_shared(&sA[buf][row][off]),
                 g_Xb + (size_t)(bi + row) * DIM + k0 + off);
            cp16((unsigned int)__cvta_generic_to_shared(&sB[buf][row][off]),
                 g_Xb + (size_t)(bj + row) * DIM + k0 + off);
        }
    };

    load_stage(0, 0);
    cp_commit();
    cp_wait0();
    __syncthreads();

    for (int s = 0; s < DIM / 32; s++) {
        const int cbuf = s & 1;
        if (s + 1 < DIM / 32) {
            load_stage((s + 1) & 1, (s + 1) * 32);
            cp_commit();
        }
#pragma unroll
        for (int ks = 0; ks < 2; ks++) {
            unsigned int a[4][4], bb[4][2];
#pragma unroll
            for (int mt = 0; mt < 4; mt++) {
                unsigned int addr = (unsigned int)__cvta_generic_to_shared(
                    &sA[cbuf][wm + mt * 16 + (lane & 15)][ks * 16 + (lane >> 4) * 8]);
                asm volatile("ldmatrix.sync.aligned.m8n8.x4.shared.b16 {%0,%1,%2,%3}, [%4];"
                             : "=r"(a[mt][0]), "=r"(a[mt][1]), "=r"(a[mt][2]), "=r"(a[mt][3])
                             : "r"(addr));
            }
#pragma unroll
            for (int nt = 0; nt < 4; nt++) {
                unsigned int addr = (unsigned int)__cvta_generic_to_shared(
                    &sB[cbuf][wn + nt * 8 + (lane & 7)][ks * 16 + ((lane >> 3) & 1) * 8]);
                asm volatile("ldmatrix.sync.aligned.m8n8.x2.shared.b16 {%0,%1}, [%2];"
                             : "=r"(bb[nt][0]), "=r"(bb[nt][1]) : "r"(addr));
            }
#pragma unroll
            for (int mt = 0; mt < 4; mt++)
#pragma unroll
                for (int nt = 0; nt < 4; nt++) {
                    asm volatile(
                        "mma.sync.aligned.m16n8k16.row.col.f32.bf16.bf16.f32 "
                        "{%0,%1,%2,%3},{%4,%5,%6,%7},{%8,%9},{%0,%1,%2,%3};"
                        : "+f"(acc[mt][nt][0]), "+f"(acc[mt][nt][1]),
                          "+f"(acc[mt][nt][2]), "+f"(acc[mt][nt][3])
                        : "r"(a[mt][0]), "r"(a[mt][1]), "r"(a[mt][2]), "r"(a[mt][3]),
                          "r"(bb[nt][0]), "r"(bb[nt][1]));
                }
        }
        if (s + 1 < DIM / 32) cp_wait0();
        __syncthreads();
    }

    // ---- direct store of (bi, bj) tile (bf16, coalesced) ----
#pragma unroll
    for (int mt = 0; mt < 4; mt++) {
#pragma unroll
        for (int nt = 0; nt < 4; nt++) {
            int r0 = bi + wm + mt * 16 + (lane >> 2);
            int c0 = bj + wn + nt * 8 + (lane & 3) * 2;
            __nv_bfloat162 p01 = __floats2bfloat162_rn(acc[mt][nt][0], acc[mt][nt][1]);
            __nv_bfloat162 p23 = __floats2bfloat162_rn(acc[mt][nt][2], acc[mt][nt][3]);
            *(__nv_bfloat162*)(g_SIMh + (size_t)r0 * NROW + c0) = p01;
            *(__nv_bfloat162*)(g_SIMh + (size_t)(r0 + 8) * NROW + c0) = p23;
        }
    }

    // ---- transposed store of (bj, bi) tile, staged via smem ----
    if (p != q) {
        for (int cc = 0; cc < 4; cc++) {
            __syncthreads();
            if ((wid & 3) == cc) {
#pragma unroll
                for (int mt = 0; mt < 4; mt++)
#pragma unroll
                    for (int nt = 0; nt < 4; nt++) {
                        int r0 = wm + mt * 16 + (lane >> 2);
                        int c0 = nt * 8 + (lane & 3) * 2;
                        tr[c0    ][r0    ] = acc[mt][nt][0];
                        tr[c0 + 1][r0    ] = acc[mt][nt][1];
                        tr[c0    ][r0 + 8] = acc[mt][nt][2];
                        tr[c0 + 1][r0 + 8] = acc[mt][nt][3];
                    }
            }
            __syncthreads();
            const int c = t >> 3;
            const int r = (t & 7) * 16;
            __nv_bfloat16* dst = g_SIMh + (size_t)(bj + cc * 32 + c) * NROW + bi + r;
#pragma unroll
            for (int k = 0; k < 4; k++) {
                float4 f = *(float4*)(&tr[c][r + k * 4]);
                __nv_bfloat162 lo = __floats2bfloat162_rn(f.x, f.y);
                __nv_bfloat162 hi = __floats2bfloat162_rn(f.z, f.w);
                uint2 w;
                w.x = *(unsigned int*)&lo;
                w.y = *(unsigned int*)&hi;
                *(uint2*)(dst + k * 4) = w;
            }
        }
    }
}

// ---------------------------------------------------------------------------
// Per-row loss on the bf16 SIM (R15-proven). 16-bit keys -> exact 2-round
// radix select; positives compacted; neg-sum scan gated on T > lower.
__global__ __launch_bounds__(NT) void row_loss_kernel() {
    __shared__ __align__(16) unsigned short s_k[NROW];    // 8 KB: neg keys (0 = not neg)
    __shared__ __align__(16) unsigned short s_pos[NROW];  // 8 KB: compact positive bf16 bits
    __shared__ unsigned int s_hist[256];
    __shared__ unsigned int s_wtot[8];
    __shared__ float        s_red[8];
    __shared__ unsigned int sh_sel, sh_r, sh_h, sh_pcnt;

    const int i    = blockIdx.x;
    const int t    = threadIdx.x;
    const int lane = t & 31;
    const int wid  = t >> 5;
    const unsigned char myc = g_cls[i];
    const __nv_bfloat16* row = g_SIMh + (size_t)i * NROW;

    s_hist[t] = 0;
    if (t == 0) sh_pcnt = 0;
    __syncthreads();

    // ---- load pass: neg keys + pos compaction + round-0 hist + K + pos_max ----
    float pmax = -1e30f;
    int   kneg = 0;
#pragma unroll
    for (int c = 0; c < 2; c++) {
        const int j0 = (c * NT + t) * 8;
        uint4 kv = *(const uint4*)(row + j0);          // 8 bf16
        uint2 cw = *(const uint2*)(g_cls + j0);        // 8 classes
        unsigned int hw[4] = {kv.x, kv.y, kv.z, kv.w};
        unsigned short kk[8];
#pragma unroll
        for (int e = 0; e < 8; e++) {
            const unsigned int u  = (hw[e >> 1] >> ((e & 1) * 16)) & 0xFFFFu;
            const unsigned int cl = ((e < 4 ? cw.x : cw.y) >> ((e & 3) * 8)) & 0xFFu;
            if (cl != (unsigned int)myc) {
                const unsigned int key = h2k(u);
                kk[e] = (unsigned short)key;
                kneg++;
                atomicAdd(&s_hist[key >> 8], 1u);
            } else {
                kk[e] = 0u;
                if (j0 + e != i) {
                    const unsigned int slot = atomicAdd(&sh_pcnt, 1u);
                    s_pos[slot] = (unsigned short)u;
                    pmax = fmaxf(pmax, h2f(u));
                }
            }
        }
        *(uint4*)(s_k + j0) = *(uint4*)kk;
    }
#pragma unroll
    for (int o = 16; o > 0; o >>= 1) {
        kneg += __shfl_xor_sync(0xFFFFFFFFu, kneg, o);
        pmax  = fmaxf(pmax, __shfl_xor_sync(0xFFFFFFFFu, pmax, o));
    }
    if (lane == 0) { s_wtot[wid] = (unsigned int)kneg; s_red[wid] = pmax; }
    __syncthreads();
    unsigned int K = 0; float pm = -1e30f;
#pragma unroll
    for (int w = 0; w < 8; w++) { K += s_wtot[w]; pm = fmaxf(pm, s_red[w]); }
    const int drop = max((int)floorf((float)K * 0.05f), 1);
    unsigned int r = (unsigned int)(drop + 1);
    const unsigned int pcnt = sh_pcnt;

    auto select_bucket = [&](unsigned int rr) {
        const unsigned int h = s_hist[t];
        unsigned int suf = h;
#pragma unroll
        for (int o = 1; o < 32; o <<= 1) {
            const unsigned int w = __shfl_down_sync(0xFFFFFFFFu, suf, o);
            if (lane + o < 32) suf += w;
        }
        if (lane == 0) s_wtot[wid] = suf;
        __syncthreads();
#pragma unroll
        for (int w = 0; w < 8; w++) if (w > wid) suf += s_wtot[w];
        if (suf >= rr && (suf - h) < rr) {
            sh_sel = (unsigned int)t;
            sh_r   = rr - (suf - h);
            sh_h   = h;
        }
        __syncthreads();
    };

    // ---- round 0 (hist already built): top byte ----
    select_bucket(r);
    unsigned int prefix = sh_sel;
    r = sh_r;
    __syncthreads();

    // ---- round 1: low byte -> full 16-bit key ----
    s_hist[t] = 0;
    __syncthreads();
#pragma unroll
    for (int c = 0; c < 2; c++) {
        const int j0 = (c * NT + t) * 8;
        uint4 kw = *(const uint4*)(s_k + j0);
        unsigned int hw[4] = {kw.x, kw.y, kw.z, kw.w};
#pragma unroll
        for (int e = 0; e < 8; e++) {
            const unsigned int k = (hw[e >> 1] >> ((e & 1) * 16)) & 0xFFFFu;
            if ((k >> 8) == prefix)
                atomicAdd(&s_hist[k & 255u], 1u);
        }
    }
    __syncthreads();
    select_bucket(r);
    const unsigned int keyT = (prefix << 8) | sh_sel;   // full key of threshold
    const float T = k2f16(keyT);                        // == neg_thresh (bf16-exact)
    const int   m = (int)sh_h + 1 - (int)sh_r;          // kept negatives equal to T
    __syncthreads();

    // ---- final: pos_loss over compact list; neg scan only if satisfiable ----
    const float thr   = T + 0.1f;
    const float lower = fmaxf(0.6f, pm) - 0.1f;
    float ploss = 0.f, ns = 0.f;

    for (unsigned int j = t; j < pcnt; j += NT) {
        const float v = h2f((unsigned int)s_pos[j]);
        if (v < thr) ploss += 1.0f - v;
    }

    if (T > lower) {
#pragma unroll
        for (int c = 0; c < 2; c++) {
            const int j0 = (c * NT + t) * 8;
            uint4 kw = *(const uint4*)(s_k + j0);
            unsigned int hw[4] = {kw.x, kw.y, kw.z, kw.w};
#pragma unroll
            for (int e = 0; e < 8; e++) {
                const unsigned int k = (hw[e >> 1] >> ((e & 1) * 16)) & 0xFFFFu;
                if (k) {
                    const float v = k2f16(k);
                    if (v < T && v > lower) ns += v;
                }
            }
        }
    }

#pragma unroll
    for (int o = 16; o > 0; o >>= 1) {
        ploss += __shfl_xor_sync(0xFFFFFFFFu, ploss, o);
        ns    += __shfl_xor_sync(0xFFFFFFFFu, ns, o);
    }
    if (lane == 0) { s_red[wid] = ploss; s_wtot[wid] = __float_as_uint(ns); }
    __syncthreads();

    if (t == 0) {
        float pl = 0.f, nss = 0.f;
#pragma unroll
        for (int w = 0; w < 8; w++) { pl += s_red[w]; nss += __uint_as_float(s_wtot[w]); }
        float loss = 0.f;
        if (pm > -1e29f) {                       // has_pos
            loss = pl + nss;
            if (T > lower) loss += (float)m * T; // ties at threshold (kept copies)
        }
        g_rowloss[i] = loss;
    }
}

// ---------------------------------------------------------------------------
__global__ void finalize_kernel(float* __restrict__ out) {
    __shared__ float s[1024];
    int t = threadIdx.x;
    float a = 0.f;
    for (int j = t; j < NROW; j += 1024) a += g_rowloss[j];
    s[t] = a; __syncthreads();
    for (int o = 512; o > 0; o >>= 1) { if (t < o) s[t] += s[t + o]; __syncthreads(); }
    if (t == 0) out[0] = s[0] / (float)NROW;
}

// ---------------------------------------------------------------------------
extern "C" void kernel_launch(void* const* d_in, const int* in_sizes, int n_in,
                              void* d_out, int out_size) {
    const float* emb   = (const float*)d_in[0];
    const int*   tgt32 = (const int*)d_in[1];
    float* out = (float*)d_out;

    normalize_kernel<<<NROW, 256>>>(emb);
    gemm_kernel<<<NGEMM + 1, 256>>>(tgt32);
    row_loss_kernel<<<NROW, NT>>>();
    finalize_kernel<<<1, 1024>>>(out);
}